// round 10
// baseline (speedup 1.0000x reference)
#include <cuda_runtime.h>

#define NB 1323        // batch rows (gaussians)
#define NPP 1323       // points per row (441*3)
#define DMODEL 1024
#define TOTAL (NB * NPP)           // 1750329 profile elements
#define LOG_2PI 1.8378770664093453f

#define PARAM_BLOCKS ((NB + 7) / 8)              // 166 (8 rows/block, warp per row)
#define PROB_GROUPS ((TOTAL + 3) / 4)            // 437583 (4 points/thread)
#define PROB_BLOCKS ((PROB_GROUPS + 255) / 256)  // 1710

// 12 floats per row (48B aligned record):
// [m0, m1, m2, inv00, L10, inv11, L20, L21, inv22, cc, pad, pad]
__device__ float g_params[NB * 12];
// Sticky ready flags: params are recomputed bit-identically every replay, so
// a reader passing a sticky flag reads identical bytes -> deterministic.
__device__ volatile int g_flags[NB];

__device__ __forceinline__ float softplus_f(float x) {
    return fmaxf(x, 0.0f) + log1pf(expf(-fabsf(x)));
}

struct RowParams {
    float m0, m1, m2, inv00, L10, inv11, L20, L21, inv22, cc;
};

__device__ __forceinline__ RowParams load_params(unsigned row) {
    const float4* pp = reinterpret_cast<const float4*>(g_params + row * 12);
    float4 q0 = pp[0];
    float4 q1 = pp[1];
    float4 q2 = pp[2];
    RowParams r;
    r.m0 = q0.x; r.m1 = q0.y; r.m2 = q0.z; r.inv00 = q0.w;
    r.L10 = q1.x; r.inv11 = q1.y; r.L20 = q1.z; r.L21 = q1.w;
    r.inv22 = q2.x; r.cc = q2.y;
    return r;
}

__device__ __forceinline__ float eval_point(const RowParams& q, float x, float y, float z) {
    float d0 = x - q.m0;
    float d1 = y - q.m1;
    float d2 = z - q.m2;
    float y0 = d0 * q.inv00;
    float y1 = fmaf(-q.L10, y0, d1) * q.inv11;
    float y2 = (d2 - fmaf(q.L20, y0, q.L21 * y1)) * q.inv22;
    float M = fmaf(y0, y0, fmaf(y1, y1, y2 * y2));
    return __expf(fmaf(-0.5f, M, q.cc));
}

// ---- param side: one warp per row, 3 passes of 3 columns to keep the live
// register set small (rep row is L1-resident after pass 0). Per-column
// summation order identical to previous rounds.
__device__ __forceinline__ void param_work(
        unsigned b, unsigned tid,
        const float* __restrict__ rep,
        const float* __restrict__ Wm,
        const float* __restrict__ bm,
        const float* __restrict__ Ws,
        const float* __restrict__ bs,
        float* __restrict__ outL) {
    unsigned wid = tid >> 5, lane = tid & 31;
    unsigned row = b * 8u + wid;
    if (row >= NB) return;

    const float4* r4 = reinterpret_cast<const float4*>(rep + (size_t)row * DMODEL);
    // Unified 9-row weight view: rows 0-2 = Wm, rows 3-8 = Ws.
    const float4* wm4 = reinterpret_cast<const float4*>(Wm);
    const float4* ws4 = reinterpret_cast<const float4*>(Ws);

    float s[9];   // reduced results (meaningful on lane 0)

#pragma unroll
    for (int g = 0; g < 3; g++) {
        float a0 = 0.0f, a1 = 0.0f, a2 = 0.0f;
#pragma unroll
        for (int it = 0; it < 8; it++) {
            int k = (int)lane + it * 32;
            float4 r = __ldg(&r4[k]);
#pragma unroll
            for (int j = 0; j < 3; j++) {
                int col = g * 3 + j;
                float4 w = (col < 3) ? __ldg(&wm4[col * (DMODEL / 4) + k])
                                     : __ldg(&ws4[(col - 3) * (DMODEL / 4) + k]);
                float v = fmaf(r.x, w.x, fmaf(r.y, w.y, fmaf(r.z, w.z, r.w * w.w)));
                if (j == 0) a0 += v; else if (j == 1) a1 += v; else a2 += v;
            }
        }
#pragma unroll
        for (int off = 16; off > 0; off >>= 1) {
            a0 += __shfl_down_sync(0xffffffffu, a0, off);
            a1 += __shfl_down_sync(0xffffffffu, a1, off);
            a2 += __shfl_down_sync(0xffffffffu, a2, off);
        }
        s[g * 3 + 0] = a0; s[g * 3 + 1] = a1; s[g * 3 + 2] = a2;
    }

    if (lane == 0) {
        float m0 = s[0] + bm[0];
        float m1 = s[1] + bm[1];
        float m2 = s[2] + bm[2];

        float L00 = softplus_f(s[3] + bs[0]);
        float L10 = s[4] + bs[1];
        float L11 = softplus_f(s[5] + bs[2]);
        float L20 = s[6] + bs[3];
        float L21 = s[7] + bs[4];
        float L22 = softplus_f(s[8] + bs[5]);

        float inv00 = __frcp_rn(L00);
        float inv11 = __frcp_rn(L11);
        float inv22 = __frcp_rn(L22);
        float cc = -1.5f * LOG_2PI - (logf(L00) + logf(L11) + logf(L22));

        float* p = g_params + row * 12;
        p[0] = m0;    p[1] = m1;    p[2] = m2;    p[3] = inv00;
        p[4] = L10;   p[5] = inv11; p[6] = L20;   p[7] = L21;
        p[8] = inv22; p[9] = cc;    p[10] = 0.0f; p[11] = 0.0f;

        // L output: (B,1,3,3): [L00,0,0, L10,L11,0, L20,L21,L22]
        float* Lo = outL + (size_t)row * 9;
        Lo[0] = L00; Lo[1] = 0.0f; Lo[2] = 0.0f;
        Lo[3] = L10; Lo[4] = L11;  Lo[5] = 0.0f;
        Lo[6] = L20; Lo[7] = L21;  Lo[8] = L22;

        __threadfence();           // release: params visible before flag
        g_flags[row] = 1;
    }
}

// ---- fused single-launch kernel, hard reg cap: 64K/(6*256)=42 regs ----
__global__ __launch_bounds__(256, 6) void mvn3d_kernel(
        const float* __restrict__ rep,
        const float* __restrict__ dxyz,
        const float* __restrict__ Wm,
        const float* __restrict__ bm,
        const float* __restrict__ Ws,
        const float* __restrict__ bs,
        float* __restrict__ outProfile,
        float* __restrict__ outL) {
    unsigned b = blockIdx.x;
    unsigned tid = threadIdx.x;

    if (b < PARAM_BLOCKS) {
        param_work(b, tid, rep, Wm, bm, Ws, bs, outL);
        return;
    }

    // ---------------- prob block ----------------
    unsigned pb = b - PARAM_BLOCKS;
    unsigned t = pb * 256u + tid;
    unsigned p0 = t * 4u;

    // Rows this BLOCK touches: 1024 consecutive points -> at most 2 rows.
    unsigned blk_p0 = pb * 1024u;
    unsigned rowLo = blk_p0 / (unsigned)NPP;
    unsigned blk_pe = min(blk_p0 + 1023u, (unsigned)TOTAL - 1u);
    unsigned rowHi = blk_pe / (unsigned)NPP;

    // Issue dxyz loads FIRST so DRAM latency overlaps the flag spin.
    float4 a, v, c;
    bool main_path = (p0 + 4u <= (unsigned)TOTAL);
    if (main_path) {
        const float4* d4 = reinterpret_cast<const float4*>(dxyz);
        a = __ldg(&d4[3u * t]);
        v = __ldg(&d4[3u * t + 1u]);
        c = __ldg(&d4[3u * t + 2u]);
    }

    // One thread spins until the (<=2) needed rows are published.
    if (tid == 0) {
        while (g_flags[rowLo] == 0) { }
        while (g_flags[rowHi] == 0) { }
        __threadfence();           // acquire
    }
    __syncthreads();

    if (p0 >= (unsigned)TOTAL) return;

    if (main_path) {
        float xs[4] = {a.x, a.w, v.z, c.y};
        float ys[4] = {a.y, v.x, v.w, c.z};
        float zs[4] = {a.z, v.y, c.x, c.w};

        unsigned i0 = p0 / (unsigned)NPP;
        unsigned i3 = (p0 + 3u) / (unsigned)NPP;
        RowParams qa = load_params(i0);
        float r[4];
        if (i0 == i3) {
#pragma unroll
            for (int u = 0; u < 4; u++)
                r[u] = eval_point(qa, xs[u], ys[u], zs[u]);
        } else {
            unsigned sB = i3 * (unsigned)NPP;
            RowParams qb = load_params(i3);
#pragma unroll
            for (int u = 0; u < 4; u++) {
                const RowParams& q = (p0 + (unsigned)u >= sB) ? qb : qa;
                r[u] = eval_point(q, xs[u], ys[u], zs[u]);
            }
        }
        reinterpret_cast<float4*>(outProfile)[t] = make_float4(r[0], r[1], r[2], r[3]);
    } else {
        // tail (TOTAL % 4 == 1): scalar path
        for (unsigned p = p0; p < (unsigned)TOTAL; p++) {
            unsigned i = p / (unsigned)NPP;
            RowParams q = load_params(i);
            outProfile[p] = eval_point(q, dxyz[3u * p], dxyz[3u * p + 1u], dxyz[3u * p + 2u]);
        }
    }
}

extern "C" void kernel_launch(void* const* d_in, const int* in_sizes, int n_in,
                              void* d_out, int out_size) {
    const float* rep  = (const float*)d_in[0];   // (B, 1024)
    const float* dxyz = (const float*)d_in[1];   // (B, NPTS, 3)
    const float* Wm   = (const float*)d_in[2];   // (3, 1024)
    const float* bm   = (const float*)d_in[3];   // (3,)
    const float* Ws   = (const float*)d_in[4];   // (6, 1024)
    const float* bs   = (const float*)d_in[5];   // (6,)
    // d_in[6] = num_planes (unused; reshape is identity)

    float* out = (float*)d_out;
    float* outProfile = out;            // TOTAL floats
    float* outL = out + TOTAL;          // NB*9 floats

    mvn3d_kernel<<<PARAM_BLOCKS + PROB_BLOCKS, 256>>>(
        rep, dxyz, Wm, bm, Ws, bs, outProfile, outL);
}

// round 11
// speedup vs baseline: 1.0683x; 1.0683x over previous
#include <cuda_runtime.h>

#define NB 1323        // batch rows (gaussians)
#define NPP 1323       // points per row (441*3)
#define DMODEL 1024
#define TOTAL (NB * NPP)           // 1750329 profile elements
#define LOG_2PI 1.8378770664093453f

// 12 floats per row (48B aligned record):
// [m0, m1, m2, inv00, L10, inv11, L20, L21, inv22, cc, pad, pad]
__device__ float g_params[NB * 12];

__device__ __forceinline__ float softplus_f(float x) {
    return fmaxf(x, 0.0f) + log1pf(expf(-fabsf(x)));
}

// PDL primitives (sm_90+)
__device__ __forceinline__ void pdl_launch_dependents() {
    asm volatile("griddepcontrol.launch_dependents;" ::: "memory");
}
__device__ __forceinline__ void pdl_wait() {
    asm volatile("griddepcontrol.wait;" ::: "memory");
}

// One 128-thread block per row (R6 shape). Each thread covers 2 float4 chunks,
// 9 dot-product partials, block reduction. Signals PDL when its row is published.
__global__ __launch_bounds__(128) void param_kernel(
        const float* __restrict__ rep,
        const float* __restrict__ Wm,
        const float* __restrict__ bm,
        const float* __restrict__ Ws,
        const float* __restrict__ bs,
        float* __restrict__ outL) {
    int row = blockIdx.x;
    int tid = threadIdx.x;          // 0..127
    int wid = tid >> 5;
    int lane = tid & 31;

    const float4* r4  = reinterpret_cast<const float4*>(rep + (size_t)row * DMODEL);
    const float4* wm4 = reinterpret_cast<const float4*>(Wm);
    const float4* ws4 = reinterpret_cast<const float4*>(Ws);

    float acc[9];
#pragma unroll
    for (int c = 0; c < 9; c++) acc[c] = 0.0f;

#pragma unroll
    for (int half = 0; half < 2; half++) {
        int k = tid + half * 128;
        float4 r = __ldg(&r4[k]);
#pragma unroll
        for (int c = 0; c < 3; c++) {
            float4 w = __ldg(&wm4[c * (DMODEL / 4) + k]);
            acc[c] = fmaf(r.x, w.x, fmaf(r.y, w.y, fmaf(r.z, w.z, fmaf(r.w, w.w, acc[c]))));
        }
#pragma unroll
        for (int c = 0; c < 6; c++) {
            float4 w = __ldg(&ws4[c * (DMODEL / 4) + k]);
            acc[3 + c] = fmaf(r.x, w.x, fmaf(r.y, w.y, fmaf(r.z, w.z, fmaf(r.w, w.w, acc[3 + c]))));
        }
    }

#pragma unroll
    for (int c = 0; c < 9; c++) {
#pragma unroll
        for (int off = 16; off > 0; off >>= 1)
            acc[c] += __shfl_down_sync(0xffffffffu, acc[c], off);
    }

    __shared__ float red[4][9];
    if (lane == 0) {
#pragma unroll
        for (int c = 0; c < 9; c++) red[wid][c] = acc[c];
    }
    __syncthreads();

    if (tid == 0) {
        float s[9];
#pragma unroll
        for (int c = 0; c < 9; c++)
            s[c] = red[0][c] + red[1][c] + red[2][c] + red[3][c];

        float m0 = s[0] + bm[0];
        float m1 = s[1] + bm[1];
        float m2 = s[2] + bm[2];

        float L00 = softplus_f(s[3] + bs[0]);
        float L10 = s[4] + bs[1];
        float L11 = softplus_f(s[5] + bs[2]);
        float L20 = s[6] + bs[3];
        float L21 = s[7] + bs[4];
        float L22 = softplus_f(s[8] + bs[5]);

        float inv00 = __frcp_rn(L00);
        float inv11 = __frcp_rn(L11);
        float inv22 = __frcp_rn(L22);
        float cc = -1.5f * LOG_2PI - (logf(L00) + logf(L11) + logf(L22));

        float* p = g_params + row * 12;
        p[0] = m0;    p[1] = m1;    p[2] = m2;    p[3] = inv00;
        p[4] = L10;   p[5] = inv11; p[6] = L20;   p[7] = L21;
        p[8] = inv22; p[9] = cc;    p[10] = 0.0f; p[11] = 0.0f;

        // L output: (B,1,3,3): [L00,0,0, L10,L11,0, L20,L21,L22]
        float* Lo = outL + (size_t)row * 9;
        Lo[0] = L00; Lo[1] = 0.0f; Lo[2] = 0.0f;
        Lo[3] = L10; Lo[4] = L11;  Lo[5] = 0.0f;
        Lo[6] = L20; Lo[7] = L21;  Lo[8] = L22;

        __threadfence();           // make row globally visible before signaling
    }
    __syncthreads();
    pdl_launch_dependents();       // allow prob grid to launch
}

struct RowParams {
    float m0, m1, m2, inv00, L10, inv11, L20, L21, inv22, cc;
};

__device__ __forceinline__ RowParams load_params(unsigned row) {
    const float4* pp = reinterpret_cast<const float4*>(g_params + row * 12);
    float4 q0 = pp[0];
    float4 q1 = pp[1];
    float4 q2 = pp[2];
    RowParams r;
    r.m0 = q0.x; r.m1 = q0.y; r.m2 = q0.z; r.inv00 = q0.w;
    r.L10 = q1.x; r.inv11 = q1.y; r.L20 = q1.z; r.L21 = q1.w;
    r.inv22 = q2.x; r.cc = q2.y;
    return r;
}

__device__ __forceinline__ float eval_point(const RowParams& q, float x, float y, float z) {
    float d0 = x - q.m0;
    float d1 = y - q.m1;
    float d2 = z - q.m2;
    float y0 = d0 * q.inv00;
    float y1 = fmaf(-q.L10, y0, d1) * q.inv11;
    float y2 = (d2 - fmaf(q.L20, y0, q.L21 * y1)) * q.inv22;
    float M = fmaf(y0, y0, fmaf(y1, y1, y2 * y2));
    return __expf(fmaf(-0.5f, M, q.cc));
}

// 4 consecutive points per thread (R6 shape). Launched with PDL: issues dxyz
// loads first, then waits for the param grid's publication, then computes.
__global__ __launch_bounds__(256) void prob_kernel(const float* __restrict__ dxyz,
                                                   float* __restrict__ out) {
    unsigned t = blockIdx.x * blockDim.x + threadIdx.x;
    unsigned p0 = t * 4u;

    if (p0 + 4u <= TOTAL) {
        const float4* d4 = reinterpret_cast<const float4*>(dxyz);
        float4 a = __ldg(&d4[3u * t]);
        float4 b = __ldg(&d4[3u * t + 1u]);
        float4 c = __ldg(&d4[3u * t + 2u]);

        pdl_wait();      // params guaranteed visible after this

        float xs[4] = {a.x, a.w, b.z, c.y};
        float ys[4] = {a.y, b.x, b.w, c.z};
        float zs[4] = {a.z, b.y, c.x, c.w};

        unsigned i0 = p0 / (unsigned)NPP;          // row of first point
        unsigned i3 = (p0 + 3u) / (unsigned)NPP;   // row of last point
        RowParams qa = load_params(i0);
        float r[4];
        if (i0 == i3) {
#pragma unroll
            for (int u = 0; u < 4; u++)
                r[u] = eval_point(qa, xs[u], ys[u], zs[u]);
        } else {
            unsigned sB = i3 * (unsigned)NPP;      // start point of next row
            RowParams qb = load_params(i3);
#pragma unroll
            for (int u = 0; u < 4; u++) {
                const RowParams& q = (p0 + (unsigned)u >= sB) ? qb : qa;
                r[u] = eval_point(q, xs[u], ys[u], zs[u]);
            }
        }
        reinterpret_cast<float4*>(out)[t] = make_float4(r[0], r[1], r[2], r[3]);
    } else if (p0 < TOTAL) {
        pdl_wait();
        // tail (TOTAL % 4 == 1): scalar path
        for (unsigned p = p0; p < TOTAL; p++) {
            unsigned i = p / (unsigned)NPP;
            RowParams q = load_params(i);
            out[p] = eval_point(q, dxyz[3u * p], dxyz[3u * p + 1u], dxyz[3u * p + 2u]);
        }
    } else {
        pdl_wait();      // uniform participation for out-of-range threads' blocks
    }
}

extern "C" void kernel_launch(void* const* d_in, const int* in_sizes, int n_in,
                              void* d_out, int out_size) {
    const float* rep  = (const float*)d_in[0];   // (B, 1024)
    const float* dxyz = (const float*)d_in[1];   // (B, NPTS, 3)
    const float* Wm   = (const float*)d_in[2];   // (3, 1024)
    const float* bm   = (const float*)d_in[3];   // (3,)
    const float* Ws   = (const float*)d_in[4];   // (6, 1024)
    const float* bs   = (const float*)d_in[5];   // (6,)
    // d_in[6] = num_planes (unused; reshape is identity)

    float* out = (float*)d_out;
    float* outProfile = out;            // TOTAL floats
    float* outL = out + TOTAL;          // NB*9 floats

    // Kernel 1: per-row params + L output. One block per row.
    param_kernel<<<NB, 128>>>(rep, Wm, bm, Ws, bs, outL);

    // Kernel 2: main probability map, launched with programmatic dependent
    // launch so its launch + dxyz load phase overlaps param_kernel.
    {
        unsigned groups = (TOTAL + 3u) / 4u;       // 437583
        unsigned blocks = (groups + 255u) / 256u;  // 1710

        cudaLaunchConfig_t cfg = {};
        cfg.gridDim = dim3(blocks, 1, 1);
        cfg.blockDim = dim3(256, 1, 1);
        cfg.dynamicSmemBytes = 0;
        cfg.stream = 0;
        cudaLaunchAttribute attrs[1];
        attrs[0].id = cudaLaunchAttributeProgrammaticStreamSerialization;
        attrs[0].val.programmaticStreamSerializationAllowed = 1;
        cfg.attrs = attrs;
        cfg.numAttrs = 1;
        cudaLaunchKernelEx(&cfg, prob_kernel, dxyz, outProfile);
    }
}